// round 1
// baseline (speedup 1.0000x reference)
#include <cuda_runtime.h>

// CombinedGeneModel: 40000 independent 1->4->1 ReLU MLPs (per tech,gene) +
// per-gene 2->1 combine. Memory-bound streaming kernel.
//
// Inputs (metadata order):
//   0: x        [B=1024, T=2, G=20000] fp32
//   1: weights1 [R=40000, E=4] fp32      (row r = t*G + g)
//   2: bias1    [R, E]
//   3: weights2 [R, E]
//   4: bias2    [R]
//   5: weights_g[G, T]
//   6: bias_g   [G]
// Output: [B, G] fp32

#define N_GENES 20000
#define N_BATCH 1024
#define BCHUNK  32          // batches per thread
#define TPB     256

__global__ __launch_bounds__(TPB) void gene_model_kernel(
    const float*  __restrict__ x,
    const float4* __restrict__ w1,   // [2G] float4 rows
    const float4* __restrict__ b1,   // [2G]
    const float4* __restrict__ w2,   // [2G]
    const float*  __restrict__ b2,   // [2G]
    const float2* __restrict__ wg,   // [G]
    const float*  __restrict__ bg,   // [G]
    float*        __restrict__ out)
{
    const int g = blockIdx.x * TPB + threadIdx.x;
    if (g >= N_GENES) return;
    const int b0 = blockIdx.y * BCHUNK;

    // Hoist this gene's weights into registers (reused across BCHUNK batches).
    const float4 w1a = w1[g],            w1b = w1[N_GENES + g];
    const float4 b1a = b1[g],            b1b = b1[N_GENES + g];
    const float4 w2a = w2[g],            w2b = w2[N_GENES + g];
    const float  b2a = b2[g],            b2b = b2[N_GENES + g];
    const float2 wgv = wg[g];
    const float  bgv = bg[g];

    const float* xp = x + (size_t)b0 * (2 * N_GENES) + g;
    float*       op = out + (size_t)b0 * N_GENES + g;

    #pragma unroll 4
    for (int i = 0; i < BCHUNK; ++i) {
        // Streaming loads: keep weights L2-resident by marking x evict-first.
        const float x0 = __ldcs(xp);             // tech 0
        const float x1 = __ldcs(xp + N_GENES);   // tech 1
        xp += 2 * N_GENES;

        // MLP for tech 0 (row g)
        float h0 = fmaxf(fmaf(x0, w1a.x, b1a.x), 0.0f);
        float h1 = fmaxf(fmaf(x0, w1a.y, b1a.y), 0.0f);
        float h2 = fmaxf(fmaf(x0, w1a.z, b1a.z), 0.0f);
        float h3 = fmaxf(fmaf(x0, w1a.w, b1a.w), 0.0f);
        float s0 = fmaf(h0, w2a.x, fmaf(h1, w2a.y,
                   fmaf(h2, w2a.z, fmaf(h3, w2a.w, b2a))));
        s0 = fmaxf(s0, 0.0f);

        // MLP for tech 1 (row G + g)
        float k0 = fmaxf(fmaf(x1, w1b.x, b1b.x), 0.0f);
        float k1 = fmaxf(fmaf(x1, w1b.y, b1b.y), 0.0f);
        float k2 = fmaxf(fmaf(x1, w1b.z, b1b.z), 0.0f);
        float k3 = fmaxf(fmaf(x1, w1b.w, b1b.w), 0.0f);
        float s1 = fmaf(k0, w2b.x, fmaf(k1, w2b.y,
                   fmaf(k2, w2b.z, fmaf(k3, w2b.w, b2b))));
        s1 = fmaxf(s1, 0.0f);

        // Per-gene combine across tech
        const float o = fmaxf(fmaf(s0, wgv.x, fmaf(s1, wgv.y, bgv)), 0.0f);
        __stcs(op, o);   // evict-first store: out is never re-read
        op += N_GENES;
    }
}

extern "C" void kernel_launch(void* const* d_in, const int* in_sizes, int n_in,
                              void* d_out, int out_size)
{
    const float*  x  = (const float*) d_in[0];
    const float4* w1 = (const float4*)d_in[1];
    const float4* b1 = (const float4*)d_in[2];
    const float4* w2 = (const float4*)d_in[3];
    const float*  b2 = (const float*) d_in[4];
    const float2* wg = (const float2*)d_in[5];
    const float*  bg = (const float*) d_in[6];
    float* out = (float*)d_out;

    dim3 grid((N_GENES + TPB - 1) / TPB, N_BATCH / BCHUNK);
    gene_model_kernel<<<grid, TPB>>>(x, w1, b1, w2, b2, wg, bg, out);
}

// round 4
// speedup vs baseline: 1.7755x; 1.7755x over previous
#include <cuda_runtime.h>

// CombinedGeneModel: 40000 independent 1->4->1 ReLU MLPs (per tech,gene) +
// per-gene 2->1 combine. Latency-bound streaming kernel -> maximize bytes
// in flight: front-batched unroll-8 load block (16 outstanding LDGs/warp).
//
// Inputs (metadata order):
//   0: x        [B=1024, T=2, G=20000] fp32
//   1: weights1 [R=40000, E=4] fp32      (row r = t*G + g)
//   2: bias1    [R, E]
//   3: weights2 [R, E]
//   4: bias2    [R]
//   5: weights_g[G, T]
//   6: bias_g   [G]
// Output: [B, G] fp32

#define N_GENES 20000
#define N_BATCH 1024
#define BCHUNK  32          // batches per thread
#define UNROLL  8           // front-batched loads per inner block
#define TPB     256

__global__ __launch_bounds__(TPB) void gene_model_kernel(
    const float*  __restrict__ x,
    const float4* __restrict__ w1,   // [2G] float4 rows
    const float4* __restrict__ b1,   // [2G]
    const float4* __restrict__ w2,   // [2G]
    const float*  __restrict__ b2,   // [2G]
    const float2* __restrict__ wg,   // [G]
    const float*  __restrict__ bg,   // [G]
    float*        __restrict__ out)
{
    const int g = blockIdx.x * TPB + threadIdx.x;
    if (g >= N_GENES) return;
    const int b0 = blockIdx.y * BCHUNK;

    // Hoist this gene's weights into registers (reused across BCHUNK batches).
    const float4 w1a = w1[g],            w1b = w1[N_GENES + g];
    const float4 b1a = b1[g],            b1b = b1[N_GENES + g];
    const float4 w2a = w2[g],            w2b = w2[N_GENES + g];
    const float  b2a = b2[g],            b2b = b2[N_GENES + g];
    const float2 wgv = wg[g];
    const float  bgv = bg[g];

    const float* xp = x + (size_t)b0 * (2 * N_GENES) + g;
    float*       op = out + (size_t)b0 * N_GENES + g;

    for (int i = 0; i < BCHUNK; i += UNROLL) {
        // ---- front-batched load block: 16 independent LDGs in flight ----
        float x0v[UNROLL], x1v[UNROLL];
        #pragma unroll
        for (int u = 0; u < UNROLL; ++u) {
            x0v[u] = __ldcs(xp + (size_t)u * (2 * N_GENES));            // tech 0
            x1v[u] = __ldcs(xp + (size_t)u * (2 * N_GENES) + N_GENES);  // tech 1
        }
        xp += (size_t)UNROLL * (2 * N_GENES);

        // ---- compute + store block ----
        #pragma unroll
        for (int u = 0; u < UNROLL; ++u) {
            const float x0 = x0v[u], x1 = x1v[u];

            // MLP for tech 0 (row g)
            float h0 = fmaxf(fmaf(x0, w1a.x, b1a.x), 0.0f);
            float h1 = fmaxf(fmaf(x0, w1a.y, b1a.y), 0.0f);
            float h2 = fmaxf(fmaf(x0, w1a.z, b1a.z), 0.0f);
            float h3 = fmaxf(fmaf(x0, w1a.w, b1a.w), 0.0f);
            float s0 = fmaf(h0, w2a.x, fmaf(h1, w2a.y,
                       fmaf(h2, w2a.z, fmaf(h3, w2a.w, b2a))));
            s0 = fmaxf(s0, 0.0f);

            // MLP for tech 1 (row G + g)
            float k0 = fmaxf(fmaf(x1, w1b.x, b1b.x), 0.0f);
            float k1 = fmaxf(fmaf(x1, w1b.y, b1b.y), 0.0f);
            float k2 = fmaxf(fmaf(x1, w1b.z, b1b.z), 0.0f);
            float k3 = fmaxf(fmaf(x1, w1b.w, b1b.w), 0.0f);
            float s1 = fmaf(k0, w2b.x, fmaf(k1, w2b.y,
                       fmaf(k2, w2b.z, fmaf(k3, w2b.w, b2b))));
            s1 = fmaxf(s1, 0.0f);

            // Per-gene combine across tech
            const float o = fmaxf(fmaf(s0, wgv.x, fmaf(s1, wgv.y, bgv)), 0.0f);
            __stcs(op + (size_t)u * N_GENES, o);  // evict-first: never re-read
        }
        op += (size_t)UNROLL * N_GENES;
    }
}

extern "C" void kernel_launch(void* const* d_in, const int* in_sizes, int n_in,
                              void* d_out, int out_size)
{
    const float*  x  = (const float*) d_in[0];
    const float4* w1 = (const float4*)d_in[1];
    const float4* b1 = (const float4*)d_in[2];
    const float4* w2 = (const float4*)d_in[3];
    const float*  b2 = (const float*) d_in[4];
    const float2* wg = (const float2*)d_in[5];
    const float*  bg = (const float*) d_in[6];
    float* out = (float*)d_out;

    dim3 grid((N_GENES + TPB - 1) / TPB, N_BATCH / BCHUNK);
    gene_model_kernel<<<grid, TPB>>>(x, w1, b1, w2, b2, wg, bg, out);
}